// round 1
// baseline (speedup 1.0000x reference)
#include <cuda_runtime.h>
#include <math.h>

#define NV   16384   // D*H*W = 16*32*32
#define CIN  256
#define CRED 128
#define ATTN_SCALE 0.0625f   // 1/sqrt(CIN)

// Scratch (device globals: allocation-free per harness rules)
__device__ float g_Q[CRED * NV];   // [Cr][N]
__device__ float g_K[CRED * NV];   // [Cr][N]
__device__ float g_V[CRED * NV];   // [Cr][N]
__device__ float g_Oa[NV * CRED];  // [N][Cr] attention output

// ---------------------------------------------------------------------------
// Kernel 1: QKV projection.  out[o][n] = sum_c W[o][c] * x[c][n] + b[o]
// grid = (N/64, 128/64, 3), block = 256.  4x4 register microtile.
// ---------------------------------------------------------------------------
__global__ __launch_bounds__(256) void qkv_kernel(
    const float* __restrict__ x,
    const float* __restrict__ Wq, const float* __restrict__ bq,
    const float* __restrict__ Wk, const float* __restrict__ bk,
    const float* __restrict__ Wv, const float* __restrict__ bv)
{
    __shared__ float Ws[64][65];   // padded: stride 65 -> conflict-free scalar access
    __shared__ float Bs[64][64];   // n-contiguous, float4-aligned

    const float* W; const float* bias; float* out;
    if (blockIdx.z == 0)      { W = Wq; bias = bq; out = g_Q; }
    else if (blockIdx.z == 1) { W = Wk; bias = bk; out = g_K; }
    else                      { W = Wv; bias = bv; out = g_V; }

    const int n0 = blockIdx.x * 64;
    const int o0 = blockIdx.y * 64;
    const int tid = threadIdx.x;
    const int tx = tid & 15, ty = tid >> 4;

    float acc[4][4] = {};

    for (int k0 = 0; k0 < CIN; k0 += 64) {
        __syncthreads();
        // Stage W tile (coalesced gmem read, conflict-free smem write)
        for (int i = tid; i < 64 * 64; i += 256) {
            int r = i >> 6, c = i & 63;
            Ws[r][c] = W[(o0 + r) * CIN + k0 + c];
        }
        // Stage x tile as Bs[k][n] (natural layout, float4)
        for (int i = tid; i < 64 * 16; i += 256) {
            int r = i >> 4, c4 = (i & 15) << 2;
            *(float4*)&Bs[r][c4] = *(const float4*)&x[(k0 + r) * NV + n0 + c4];
        }
        __syncthreads();
        #pragma unroll 16
        for (int kk = 0; kk < 64; kk++) {
            float a0 = Ws[4*ty+0][kk];
            float a1 = Ws[4*ty+1][kk];
            float a2 = Ws[4*ty+2][kk];
            float a3 = Ws[4*ty+3][kk];
            float4 b = *(float4*)&Bs[kk][4*tx];
            acc[0][0] += a0*b.x; acc[0][1] += a0*b.y; acc[0][2] += a0*b.z; acc[0][3] += a0*b.w;
            acc[1][0] += a1*b.x; acc[1][1] += a1*b.y; acc[1][2] += a1*b.z; acc[1][3] += a1*b.w;
            acc[2][0] += a2*b.x; acc[2][1] += a2*b.y; acc[2][2] += a2*b.z; acc[2][3] += a2*b.w;
            acc[3][0] += a3*b.x; acc[3][1] += a3*b.y; acc[3][2] += a3*b.z; acc[3][3] += a3*b.w;
        }
    }
    #pragma unroll
    for (int i = 0; i < 4; i++) {
        int o = o0 + 4*ty + i;
        float bb = bias[o];
        float4 r;
        r.x = acc[i][0] + bb;
        r.y = acc[i][1] + bb;
        r.z = acc[i][2] + bb;
        r.w = acc[i][3] + bb;
        *(float4*)&out[o * NV + n0 + 4*tx] = r;
    }
}

// ---------------------------------------------------------------------------
// Kernel 2: flash attention, fp32.  One CTA per 64-row Q tile, 256 threads.
// S microtile 4x4 per thread (rows 4ty.., cols 4tx..); O microtile 4 rows x
// 8 d-dims (d = tx + 16j).  Dynamic SMEM: Qs/Ks [128][64], Vs [128][65],
// Ps [64][65].
// ---------------------------------------------------------------------------
extern __shared__ float smem_attn[];

__global__ __launch_bounds__(256) void attn_kernel()
{
    float* Qs = smem_attn;              // [128][64]
    float* Ks = Qs + 128 * 64;          // [128][64]
    float* Vs = Ks + 128 * 64;          // [128][65] padded
    float* Ps = Vs + 128 * 65;          // [64][65]  padded

    const int n0 = blockIdx.x * 64;
    const int tid = threadIdx.x;
    const int tx = tid & 15, ty = tid >> 4;

    // Stage Q tile once, folding the softmax scale into Q.
    for (int i = tid; i < 128 * 16; i += 256) {
        int d = i >> 4, r4 = (i & 15) << 2;
        float4 q = *(const float4*)&g_Q[d * NV + n0 + r4];
        q.x *= ATTN_SCALE; q.y *= ATTN_SCALE; q.z *= ATTN_SCALE; q.w *= ATTN_SCALE;
        *(float4*)&Qs[d * 64 + r4] = q;
    }

    float m[4], l[4], acc[4][8];
    #pragma unroll
    for (int i = 0; i < 4; i++) {
        m[i] = -1e30f; l[i] = 0.0f;
        #pragma unroll
        for (int j = 0; j < 8; j++) acc[i][j] = 0.0f;
    }

    for (int kt = 0; kt < NV; kt += 64) {
        __syncthreads();   // protects Ks/Vs from previous iteration's readers
        for (int i = tid; i < 128 * 16; i += 256) {
            int d = i >> 4, c4 = (i & 15) << 2;
            *(float4*)&Ks[d * 64 + c4] = *(const float4*)&g_K[d * NV + kt + c4];
        }
        for (int i = tid; i < 128 * 64; i += 256) {
            int d = i >> 6, c = i & 63;           // lanes vary c: coalesced, conflict-free
            Vs[d * 65 + c] = g_V[d * NV + kt + c];
        }
        __syncthreads();

        // S = (Q*scale) @ K^T  over d=128
        float s[4][4] = {};
        #pragma unroll 8
        for (int d = 0; d < 128; d++) {
            float4 a = *(float4*)&Qs[d * 64 + 4*ty];   // 2 addrs/warp -> broadcast
            float4 b = *(float4*)&Ks[d * 64 + 4*tx];
            s[0][0]+=a.x*b.x; s[0][1]+=a.x*b.y; s[0][2]+=a.x*b.z; s[0][3]+=a.x*b.w;
            s[1][0]+=a.y*b.x; s[1][1]+=a.y*b.y; s[1][2]+=a.y*b.z; s[1][3]+=a.y*b.w;
            s[2][0]+=a.z*b.x; s[2][1]+=a.z*b.y; s[2][2]+=a.z*b.z; s[2][3]+=a.z*b.w;
            s[3][0]+=a.w*b.x; s[3][1]+=a.w*b.y; s[3][2]+=a.w*b.z; s[3][3]+=a.w*b.w;
        }

        // Online softmax (row groups = 16 tx threads, lane bits 0-3)
        #pragma unroll
        for (int i = 0; i < 4; i++) {
            float mx = fmaxf(fmaxf(s[i][0], s[i][1]), fmaxf(s[i][2], s[i][3]));
            #pragma unroll
            for (int off = 1; off < 16; off <<= 1)
                mx = fmaxf(mx, __shfl_xor_sync(0xffffffffu, mx, off));
            float mnew = fmaxf(m[i], mx);
            float f = __expf(m[i] - mnew);
            m[i] = mnew;
            l[i] *= f;
            #pragma unroll
            for (int j = 0; j < 8; j++) acc[i][j] *= f;
            float rs = 0.0f;
            #pragma unroll
            for (int j = 0; j < 4; j++) {
                float p = __expf(s[i][j] - mnew);
                Ps[(4*ty + i) * 65 + 4*tx + j] = p;
                rs += p;
            }
            #pragma unroll
            for (int off = 1; off < 16; off <<= 1)
                rs += __shfl_xor_sync(0xffffffffu, rs, off);
            l[i] += rs;
        }
        __syncthreads();   // Ps visible to the whole row group

        // O += P @ V   (thread owns d = tx + 16j, j=0..7)
        #pragma unroll 2
        for (int c = 0; c < 64; c++) {
            float p0 = Ps[(4*ty + 0) * 65 + c];
            float p1 = Ps[(4*ty + 1) * 65 + c];
            float p2 = Ps[(4*ty + 2) * 65 + c];
            float p3 = Ps[(4*ty + 3) * 65 + c];
            #pragma unroll
            for (int j = 0; j < 8; j++) {
                float v = Vs[(tx + 16*j) * 65 + c];  // banks (tx+16j+c): conflict-free
                acc[0][j] += p0 * v;
                acc[1][j] += p1 * v;
                acc[2][j] += p2 * v;
                acc[3][j] += p3 * v;
            }
        }
    }

    #pragma unroll
    for (int i = 0; i < 4; i++) {
        float inv = 1.0f / l[i];
        #pragma unroll
        for (int j = 0; j < 8; j++)
            g_Oa[(n0 + 4*ty + i) * CRED + tx + 16*j] = acc[i][j] * inv;
    }
}

// ---------------------------------------------------------------------------
// Kernel 3: output projection + residual.
// out[o][n] = x[o][n] + sum_k Wo[o][k] * g_Oa[n][k] + bo[o]
// grid = (N/64, 256/64), block = 256.
// ---------------------------------------------------------------------------
__global__ __launch_bounds__(256) void proj_kernel(
    const float* __restrict__ x, const float* __restrict__ Wo,
    const float* __restrict__ bo, float* __restrict__ out)
{
    __shared__ float Ws[64][65];
    __shared__ float Bs[64][65];

    const int n0 = blockIdx.x * 64;
    const int o0 = blockIdx.y * 64;
    const int tid = threadIdx.x;
    const int tx = tid & 15, ty = tid >> 4;

    float acc[4][4] = {};

    for (int k0 = 0; k0 < CRED; k0 += 64) {
        __syncthreads();
        for (int i = tid; i < 4096; i += 256) {
            int r = i >> 6, c = i & 63;
            Ws[r][c] = Wo[(o0 + r) * CRED + k0 + c];
        }
        // Transpose g_Oa tile into Bs[k][n] (lanes vary k: coalesced read,
        // smem bank = (k + n) mod 32: conflict-free write)
        for (int i = tid; i < 4096; i += 256) {
            int n = i >> 6, k = i & 63;
            Bs[k][n] = g_Oa[(n0 + n) * CRED + k0 + k];
        }
        __syncthreads();
        #pragma unroll 16
        for (int kk = 0; kk < 64; kk++) {
            float a0 = Ws[4*ty+0][kk];
            float a1 = Ws[4*ty+1][kk];
            float a2 = Ws[4*ty+2][kk];
            float a3 = Ws[4*ty+3][kk];
            float b0 = Bs[kk][4*tx+0];
            float b1 = Bs[kk][4*tx+1];
            float b2 = Bs[kk][4*tx+2];
            float b3 = Bs[kk][4*tx+3];
            acc[0][0] += a0*b0; acc[0][1] += a0*b1; acc[0][2] += a0*b2; acc[0][3] += a0*b3;
            acc[1][0] += a1*b0; acc[1][1] += a1*b1; acc[1][2] += a1*b2; acc[1][3] += a1*b3;
            acc[2][0] += a2*b0; acc[2][1] += a2*b1; acc[2][2] += a2*b2; acc[2][3] += a2*b3;
            acc[3][0] += a3*b0; acc[3][1] += a3*b1; acc[3][2] += a3*b2; acc[3][3] += a3*b3;
        }
    }
    #pragma unroll
    for (int i = 0; i < 4; i++) {
        int o = o0 + 4*ty + i;
        float bb = bo[o];
        const float4 xi = *(const float4*)&x[o * NV + n0 + 4*tx];
        float4 r;
        r.x = xi.x + acc[i][0] + bb;
        r.y = xi.y + acc[i][1] + bb;
        r.z = xi.z + acc[i][2] + bb;
        r.w = xi.w + acc[i][3] + bb;
        *(float4*)&out[o * NV + n0 + 4*tx] = r;
    }
}

// ---------------------------------------------------------------------------
extern "C" void kernel_launch(void* const* d_in, const int* in_sizes, int n_in,
                              void* d_out, int out_size)
{
    const float* x  = (const float*)d_in[0];
    const float* Wq = (const float*)d_in[1];
    const float* bq = (const float*)d_in[2];
    const float* Wk = (const float*)d_in[3];
    const float* bk = (const float*)d_in[4];
    const float* Wv = (const float*)d_in[5];
    const float* bv = (const float*)d_in[6];
    const float* Wo = (const float*)d_in[7];
    const float* bo = (const float*)d_in[8];
    float* out = (float*)d_out;

    qkv_kernel<<<dim3(NV/64, 2, 3), 256>>>(x, Wq, bq, Wk, bk, Wv, bv);

    const int attn_smem = (128*64 + 128*64 + 128*65 + 64*65) * (int)sizeof(float); // 115456 B
    cudaFuncSetAttribute(attn_kernel, cudaFuncAttributeMaxDynamicSharedMemorySize, attn_smem);
    attn_kernel<<<NV/64, 256, attn_smem>>>();

    proj_kernel<<<dim3(NV/64, CIN/64), 256>>>(x, Wo, bo, out);
}

// round 3
// speedup vs baseline: 4.5958x; 4.5958x over previous
#include <cuda_runtime.h>
#include <cuda_bf16.h>
#include <cstdint>
#include <math.h>

#define NV   16384   // D*H*W
#define CIN  256
#define CRED 128
#define ATTN_SCALE 0.0625f   // 1/sqrt(CIN)

// Scratch (device globals, allocation-free)
__device__ __align__(16) float g_Q[CRED * NV];   // [d][N] fp32
__device__ __align__(16) float g_K[CRED * NV];
__device__ __align__(16) float g_V[CRED * NV];
__device__ __align__(16) float g_Oa[NV * CRED];  // [N][d] attention out fp32
__device__ __align__(16) __nv_bfloat16 g_Qh[NV * CRED];  // [n][d], pre-scaled
__device__ __align__(16) __nv_bfloat16 g_Kh[NV * CRED];  // [n][d]
__device__ __align__(16) __nv_bfloat16 g_Vh[CRED * NV];  // [d][n]

// ---------------------------------------------------------------------------
// PTX helpers
// ---------------------------------------------------------------------------
__device__ __forceinline__ uint32_t smem_u32(const void* p) {
    return (uint32_t)__cvta_generic_to_shared(p);
}
#define CP_ASYNC16(dst, src) \
    asm volatile("cp.async.cg.shared.global [%0], [%1], 16;\n" :: "r"(dst), "l"(src))
#define CP_COMMIT() asm volatile("cp.async.commit_group;\n" ::: "memory")
#define CP_WAIT0()  asm volatile("cp.async.wait_group 0;\n" ::: "memory")

#define LDSM4(r0, r1, r2, r3, addr) \
    asm volatile("ldmatrix.sync.aligned.m8n8.x4.shared.b16 {%0,%1,%2,%3}, [%4];" \
                 : "=r"(r0), "=r"(r1), "=r"(r2), "=r"(r3) : "r"(addr))

#define MMA16816(c, a0, a1, a2, a3, b0, b1) \
    asm volatile("mma.sync.aligned.m16n8k16.row.col.f32.bf16.bf16.f32 " \
                 "{%0,%1,%2,%3}, {%4,%5,%6,%7}, {%8,%9}, {%0,%1,%2,%3};" \
                 : "+f"(c[0]), "+f"(c[1]), "+f"(c[2]), "+f"(c[3]) \
                 : "r"(a0), "r"(a1), "r"(a2), "r"(a3), "r"(b0), "r"(b1))

__device__ __forceinline__ uint32_t packbf(float lo, float hi) {
    uint32_t d;
    asm("cvt.rn.bf16x2.f32 %0, %1, %2;" : "=r"(d) : "f"(hi), "f"(lo));
    return d;
}

// ---------------------------------------------------------------------------
// Kernel 1: QKV projection (fp32).  out[o][n] = sum_c W[o][c]*x[c][n] + b[o]
// ---------------------------------------------------------------------------
__global__ __launch_bounds__(256) void qkv_kernel(
    const float* __restrict__ x,
    const float* __restrict__ Wq, const float* __restrict__ bq,
    const float* __restrict__ Wk, const float* __restrict__ bk,
    const float* __restrict__ Wv, const float* __restrict__ bv)
{
    __shared__ float Ws[64][65];
    __shared__ float Bs[64][64];

    const float* W; const float* bias; float* out;
    if (blockIdx.z == 0)      { W = Wq; bias = bq; out = g_Q; }
    else if (blockIdx.z == 1) { W = Wk; bias = bk; out = g_K; }
    else                      { W = Wv; bias = bv; out = g_V; }

    const int n0 = blockIdx.x * 64;
    const int o0 = blockIdx.y * 64;
    const int tid = threadIdx.x;
    const int tx = tid & 15, ty = tid >> 4;

    float acc[4][4] = {};

    for (int k0 = 0; k0 < CIN; k0 += 64) {
        __syncthreads();
        for (int i = tid; i < 64 * 64; i += 256) {
            int r = i >> 6, c = i & 63;
            Ws[r][c] = W[(o0 + r) * CIN + k0 + c];
        }
        for (int i = tid; i < 64 * 16; i += 256) {
            int r = i >> 4, c4 = (i & 15) << 2;
            *(float4*)&Bs[r][c4] = *(const float4*)&x[(k0 + r) * NV + n0 + c4];
        }
        __syncthreads();
        #pragma unroll 16
        for (int kk = 0; kk < 64; kk++) {
            float a0 = Ws[4*ty+0][kk], a1 = Ws[4*ty+1][kk];
            float a2 = Ws[4*ty+2][kk], a3 = Ws[4*ty+3][kk];
            float4 b = *(float4*)&Bs[kk][4*tx];
            acc[0][0]+=a0*b.x; acc[0][1]+=a0*b.y; acc[0][2]+=a0*b.z; acc[0][3]+=a0*b.w;
            acc[1][0]+=a1*b.x; acc[1][1]+=a1*b.y; acc[1][2]+=a1*b.z; acc[1][3]+=a1*b.w;
            acc[2][0]+=a2*b.x; acc[2][1]+=a2*b.y; acc[2][2]+=a2*b.z; acc[2][3]+=a2*b.w;
            acc[3][0]+=a3*b.x; acc[3][1]+=a3*b.y; acc[3][2]+=a3*b.z; acc[3][3]+=a3*b.w;
        }
    }
    #pragma unroll
    for (int i = 0; i < 4; i++) {
        int o = o0 + 4*ty + i;
        float bb = bias[o];
        float4 r;
        r.x = acc[i][0]+bb; r.y = acc[i][1]+bb; r.z = acc[i][2]+bb; r.w = acc[i][3]+bb;
        *(float4*)&out[o * NV + n0 + 4*tx] = r;
    }
}

// ---------------------------------------------------------------------------
// Kernel 1b: transpose+convert Q,K: fp32 [d][N] -> bf16 [n][128]
// grid (NV/64, CRED/64, 2)
// ---------------------------------------------------------------------------
__global__ __launch_bounds__(256) void cvt_qk_kernel()
{
    __shared__ float ts[64][65];
    const float* src = blockIdx.z ? g_K : g_Q;
    __nv_bfloat16* dst = blockIdx.z ? g_Kh : g_Qh;
    const float scale = blockIdx.z ? 1.0f : ATTN_SCALE;
    const int n0 = blockIdx.x * 64, d0 = blockIdx.y * 64;
    const int tid = threadIdx.x;

    for (int i = tid; i < 4096; i += 256) {
        int r = i >> 6, c = i & 63;                       // r = d, c = n (coalesced)
        ts[r][c] = src[(d0 + r) * NV + n0 + c] * scale;
    }
    __syncthreads();
    for (int i = tid; i < 2048; i += 256) {
        int n = i >> 5, w = i & 31;
        __nv_bfloat162 v = __floats2bfloat162_rn(ts[2*w][n], ts[2*w+1][n]);
        *(__nv_bfloat162*)&dst[(n0 + n) * CRED + d0 + 2*w] = v;
    }
}

// Kernel 1c: elementwise convert V fp32 [d][N] -> bf16 [d][N]
__global__ __launch_bounds__(256) void cvt_v_kernel()
{
    int i = blockIdx.x * 256 + threadIdx.x;   // one float4 each
    float4 v = *(const float4*)&g_V[i * 4];
    __nv_bfloat162 lo = __floats2bfloat162_rn(v.x, v.y);
    __nv_bfloat162 hi = __floats2bfloat162_rn(v.z, v.w);
    uint2 pk = make_uint2(*(uint32_t*)&lo, *(uint32_t*)&hi);
    *(uint2*)&g_Vh[i * 4] = pk;
}

// ---------------------------------------------------------------------------
// Kernel 2: bf16 flash attention with mma.sync.m16n8k16.
// CTA: 128 Q rows, 8 warps (16 rows each). KV tile = 64, double-buffered.
// SMEM (dynamic, 96KB): Qs[128][128] (swizzled), Ks[2][64][128], Vs[2][128][64]
// Q/K rows: 256B = 16 chunks of 16B, swizzle chunk c -> c ^ (row&7).
// V rows (d): 128B = 8 chunks, same swizzle.
// ---------------------------------------------------------------------------
extern __shared__ char sm_attn[];

__global__ __launch_bounds__(256, 1) void attn_kernel()
{
    const uint32_t sbase = smem_u32(sm_attn);
    const uint32_t QS = sbase;
    const uint32_t KS0 = sbase + 32768, KS1 = sbase + 49152;
    const uint32_t VS0 = sbase + 65536, VS1 = sbase + 81920;

    const int tid = threadIdx.x;
    const int lane = tid & 31, warp = tid >> 5;
    const int n0 = blockIdx.x * 128;
    const int wr = warp * 16;                 // warp's row base within tile
    const int lr = lane & 7, g = lane >> 3;   // ldmatrix lane decomposition

    // Stage Q (once)
    for (int i = tid; i < 2048; i += 256) {
        int r = i >> 4, cc = i & 15;
        uint32_t dst = QS + r * 256 + ((cc ^ (r & 7)) << 4);
        CP_ASYNC16(dst, &g_Qh[(n0 + r) * CRED + cc * 8]);
    }
    // Stage K/V tile 0
    {
        for (int i = tid; i < 1024; i += 256) {
            int r = i >> 4, cc = i & 15;
            CP_ASYNC16(KS0 + r * 256 + ((cc ^ (r & 7)) << 4), &g_Kh[r * CRED + cc * 8]);
        }
        for (int i = tid; i < 1024; i += 256) {
            int r = i >> 3, cc = i & 7;
            CP_ASYNC16(VS0 + r * 128 + ((cc ^ (r & 7)) << 4), &g_Vh[r * NV + cc * 8]);
        }
    }
    CP_COMMIT();

    float oAcc[16][4];
    #pragma unroll
    for (int i = 0; i < 16; i++) { oAcc[i][0]=0; oAcc[i][1]=0; oAcc[i][2]=0; oAcc[i][3]=0; }
    float m0 = -1e30f, m1 = -1e30f, l0 = 0.0f, l1 = 0.0f;

    const int T = NV / 64;   // 256 kv tiles
    for (int t = 0; t < T; t++) {
        CP_WAIT0();
        __syncthreads();
        const uint32_t KS = (t & 1) ? KS1 : KS0;
        const uint32_t VS = (t & 1) ? VS1 : VS0;
        if (t + 1 < T) {
            const int kt = (t + 1) * 64;
            const uint32_t KSn = (t & 1) ? KS0 : KS1;
            const uint32_t VSn = (t & 1) ? VS0 : VS1;
            for (int i = tid; i < 1024; i += 256) {
                int r = i >> 4, cc = i & 15;
                CP_ASYNC16(KSn + r * 256 + ((cc ^ (r & 7)) << 4),
                           &g_Kh[(kt + r) * CRED + cc * 8]);
            }
            for (int i = tid; i < 1024; i += 256) {
                int r = i >> 3, cc = i & 7;
                CP_ASYNC16(VSn + r * 128 + ((cc ^ (r & 7)) << 4),
                           &g_Vh[r * NV + kt + cc * 8]);
            }
            CP_COMMIT();
        }

        // ---- S = Q @ K^T (16 rows x 64 cols per warp) ----
        float sAcc[8][4];
        #pragma unroll
        for (int i = 0; i < 8; i++) { sAcc[i][0]=0; sAcc[i][1]=0; sAcc[i][2]=0; sAcc[i][3]=0; }

        #pragma unroll
        for (int kk = 0; kk < 8; kk++) {
            int arow = wr + lr + ((g & 1) << 3);
            int akc = (kk << 1) + (g >> 1);
            uint32_t a0, a1, a2, a3;
            LDSM4(a0, a1, a2, a3, QS + arow * 256 + ((akc ^ (arow & 7)) << 4));
            #pragma unroll
            for (int np = 0; np < 4; np++) {
                int brow = (np << 4) + lr + ((g >> 1) << 3);
                int bkc = (kk << 1) + (g & 1);
                uint32_t b0, b1, b2, b3;
                LDSM4(b0, b1, b2, b3, KS + brow * 256 + ((bkc ^ (brow & 7)) << 4));
                MMA16816(sAcc[2*np],   a0, a1, a2, a3, b0, b1);
                MMA16816(sAcc[2*np+1], a0, a1, a2, a3, b2, b3);
            }
        }

        // ---- online softmax (rows: lo = wr + lane/4, hi = +8) ----
        float mx0 = -1e30f, mx1 = -1e30f;
        #pragma unroll
        for (int nt = 0; nt < 8; nt++) {
            mx0 = fmaxf(mx0, fmaxf(sAcc[nt][0], sAcc[nt][1]));
            mx1 = fmaxf(mx1, fmaxf(sAcc[nt][2], sAcc[nt][3]));
        }
        mx0 = fmaxf(mx0, __shfl_xor_sync(0xffffffffu, mx0, 1));
        mx0 = fmaxf(mx0, __shfl_xor_sync(0xffffffffu, mx0, 2));
        mx1 = fmaxf(mx1, __shfl_xor_sync(0xffffffffu, mx1, 1));
        mx1 = fmaxf(mx1, __shfl_xor_sync(0xffffffffu, mx1, 2));
        float mn0 = fmaxf(m0, mx0), mn1 = fmaxf(m1, mx1);
        float f0 = __expf(m0 - mn0), f1 = __expf(m1 - mn1);
        m0 = mn0; m1 = mn1;
        l0 *= f0; l1 *= f1;
        float s0 = 0.0f, s1 = 0.0f;
        #pragma unroll
        for (int nt = 0; nt < 8; nt++) {
            float p;
            p = __expf(sAcc[nt][0] - m0); sAcc[nt][0] = p; s0 += p;
            p = __expf(sAcc[nt][1] - m0); sAcc[nt][1] = p; s0 += p;
            p = __expf(sAcc[nt][2] - m1); sAcc[nt][2] = p; s1 += p;
            p = __expf(sAcc[nt][3] - m1); sAcc[nt][3] = p; s1 += p;
        }
        l0 += s0; l1 += s1;
        #pragma unroll
        for (int dt = 0; dt < 16; dt++) {
            oAcc[dt][0] *= f0; oAcc[dt][1] *= f0;
            oAcc[dt][2] *= f1; oAcc[dt][3] *= f1;
        }

        // ---- O += P @ V ----
        #pragma unroll
        for (int kk = 0; kk < 4; kk++) {
            uint32_t a0 = packbf(sAcc[2*kk][0],   sAcc[2*kk][1]);
            uint32_t a1 = packbf(sAcc[2*kk][2],   sAcc[2*kk][3]);
            uint32_t a2 = packbf(sAcc[2*kk+1][0], sAcc[2*kk+1][1]);
            uint32_t a3 = packbf(sAcc[2*kk+1][2], sAcc[2*kk+1][3]);
            #pragma unroll
            for (int dp = 0; dp < 8; dp++) {
                int vrow = (dp << 4) + lr + ((g >> 1) << 3);
                int vkc = (kk << 1) + (g & 1);
                uint32_t b0, b1, b2, b3;
                LDSM4(b0, b1, b2, b3, VS + vrow * 128 + ((vkc ^ (vrow & 7)) << 4));
                MMA16816(oAcc[2*dp],   a0, a1, a2, a3, b0, b1);
                MMA16816(oAcc[2*dp+1], a0, a1, a2, a3, b2, b3);
            }
        }
        __syncthreads();
    }

    // epilogue: full row sums, normalize, write fp32 [N][128]
    l0 += __shfl_xor_sync(0xffffffffu, l0, 1);
    l0 += __shfl_xor_sync(0xffffffffu, l0, 2);
    l1 += __shfl_xor_sync(0xffffffffu, l1, 1);
    l1 += __shfl_xor_sync(0xffffffffu, l1, 2);
    const float inv0 = 1.0f / l0, inv1 = 1.0f / l1;
    const int row_lo = n0 + wr + (lane >> 2);
    const int row_hi = row_lo + 8;
    #pragma unroll
    for (int dt = 0; dt < 16; dt++) {
        int d = dt * 8 + 2 * (lane & 3);
        float2 vlo = make_float2(oAcc[dt][0] * inv0, oAcc[dt][1] * inv0);
        float2 vhi = make_float2(oAcc[dt][2] * inv1, oAcc[dt][3] * inv1);
        *(float2*)&g_Oa[row_lo * CRED + d] = vlo;
        *(float2*)&g_Oa[row_hi * CRED + d] = vhi;
    }
}

// ---------------------------------------------------------------------------
// Kernel 3: output projection + residual (fp32)
// ---------------------------------------------------------------------------
__global__ __launch_bounds__(256) void proj_kernel(
    const float* __restrict__ x, const float* __restrict__ Wo,
    const float* __restrict__ bo, float* __restrict__ out)
{
    __shared__ float Ws[64][65];
    __shared__ float Bs[64][65];

    const int n0 = blockIdx.x * 64;
    const int o0 = blockIdx.y * 64;
    const int tid = threadIdx.x;
    const int tx = tid & 15, ty = tid >> 4;

    float acc[4][4] = {};

    for (int k0 = 0; k0 < CRED; k0 += 64) {
        __syncthreads();
        for (int i = tid; i < 4096; i += 256) {
            int r = i >> 6, c = i & 63;
            Ws[r][c] = Wo[(o0 + r) * CRED + k0 + c];
        }
        for (int i = tid; i < 4096; i += 256) {
            int n = i >> 6, k = i & 63;
            Bs[k][n] = g_Oa[(n0 + n) * CRED + k0 + k];
        }
        __syncthreads();
        #pragma unroll 16
        for (int kk = 0; kk < 64; kk++) {
            float a0 = Ws[4*ty+0][kk], a1 = Ws[4*ty+1][kk];
            float a2 = Ws[4*ty+2][kk], a3 = Ws[4*ty+3][kk];
            float b0 = Bs[kk][4*tx+0], b1 = Bs[kk][4*tx+1];
            float b2 = Bs[kk][4*tx+2], b3 = Bs[kk][4*tx+3];
            acc[0][0]+=a0*b0; acc[0][1]+=a0*b1; acc[0][2]+=a0*b2; acc[0][3]+=a0*b3;
            acc[1][0]+=a1*b0; acc[1][1]+=a1*b1; acc[1][2]+=a1*b2; acc[1][3]+=a1*b3;
            acc[2][0]+=a2*b0; acc[2][1]+=a2*b1; acc[2][2]+=a2*b2; acc[2][3]+=a2*b3;
            acc[3][0]+=a3*b0; acc[3][1]+=a3*b1; acc[3][2]+=a3*b2; acc[3][3]+=a3*b3;
        }
    }
    #pragma unroll
    for (int i = 0; i < 4; i++) {
        int o = o0 + 4*ty + i;
        float bb = bo[o];
        const float4 xi = *(const float4*)&x[o * NV + n0 + 4*tx];
        float4 r;
        r.x = xi.x + acc[i][0] + bb;
        r.y = xi.y + acc[i][1] + bb;
        r.z = xi.z + acc[i][2] + bb;
        r.w = xi.w + acc[i][3] + bb;
        *(float4*)&out[o * NV + n0 + 4*tx] = r;
    }
}

// ---------------------------------------------------------------------------
extern "C" void kernel_launch(void* const* d_in, const int* in_sizes, int n_in,
                              void* d_out, int out_size)
{
    const float* x  = (const float*)d_in[0];
    const float* Wq = (const float*)d_in[1];
    const float* bq = (const float*)d_in[2];
    const float* Wk = (const float*)d_in[3];
    const float* bk = (const float*)d_in[4];
    const float* Wv = (const float*)d_in[5];
    const float* bv = (const float*)d_in[6];
    const float* Wo = (const float*)d_in[7];
    const float* bo = (const float*)d_in[8];
    float* out = (float*)d_out;

    qkv_kernel<<<dim3(NV/64, 2, 3), 256>>>(x, Wq, bq, Wk, bk, Wv, bv);
    cvt_qk_kernel<<<dim3(NV/64, CRED/64, 2), 256>>>();
    cvt_v_kernel<<<(CRED * NV / 4) / 256, 256>>>();

    const int attn_smem = 98304;
    cudaFuncSetAttribute(attn_kernel, cudaFuncAttributeMaxDynamicSharedMemorySize, attn_smem);
    attn_kernel<<<NV/128, 256, attn_smem>>>();

    proj_kernel<<<dim3(NV/64, CIN/64), 256>>>(x, Wo, bo, out);
}

// round 4
// speedup vs baseline: 7.5633x; 1.6457x over previous
#include <cuda_runtime.h>
#include <cuda_bf16.h>
#include <cstdint>
#include <math.h>

#define NV   16384   // D*H*W
#define CIN  256
#define CRED 128
#define ATTN_SCALE 0.0625f   // 1/sqrt(CIN)

// Scratch (device globals, allocation-free)
__device__ __align__(16) float g_Oa[NV * CRED];          // [N][d] attention out fp32
__device__ __align__(16) __nv_bfloat16 g_Qh[NV * CRED];  // [n][d], pre-scaled
__device__ __align__(16) __nv_bfloat16 g_Kh[NV * CRED];  // [n][d]
__device__ __align__(16) __nv_bfloat16 g_Vh[CRED * NV];  // [d][n]

// ---------------------------------------------------------------------------
// PTX helpers
// ---------------------------------------------------------------------------
__device__ __forceinline__ uint32_t smem_u32(const void* p) {
    return (uint32_t)__cvta_generic_to_shared(p);
}
#define CP_ASYNC16(dst, src) \
    asm volatile("cp.async.cg.shared.global [%0], [%1], 16;\n" :: "r"(dst), "l"(src))
#define CP_COMMIT() asm volatile("cp.async.commit_group;\n" ::: "memory")
#define CP_WAIT0()  asm volatile("cp.async.wait_group 0;\n" ::: "memory")

#define LDSM4(r0, r1, r2, r3, addr) \
    asm volatile("ldmatrix.sync.aligned.m8n8.x4.shared.b16 {%0,%1,%2,%3}, [%4];" \
                 : "=r"(r0), "=r"(r1), "=r"(r2), "=r"(r3) : "r"(addr))

#define MMA16816(c, a0, a1, a2, a3, b0, b1) \
    asm volatile("mma.sync.aligned.m16n8k16.row.col.f32.bf16.bf16.f32 " \
                 "{%0,%1,%2,%3}, {%4,%5,%6,%7}, {%8,%9}, {%0,%1,%2,%3};" \
                 : "+f"(c[0]), "+f"(c[1]), "+f"(c[2]), "+f"(c[3]) \
                 : "r"(a0), "r"(a1), "r"(a2), "r"(a3), "r"(b0), "r"(b1))

__device__ __forceinline__ uint32_t packbf(float lo, float hi) {
    uint32_t d;
    asm("cvt.rn.bf16x2.f32 %0, %1, %2;" : "=r"(d) : "f"(hi), "f"(lo));
    return d;
}

// ---------------------------------------------------------------------------
// Kernel 1: QKV projection, fused bf16 output.
//   z=0: Qh[n][d] = scale*(Wq x + bq)   (smem transpose)
//   z=1: Kh[n][d] =        Wk x + bk    (smem transpose)
//   z=2: Vh[d][n] =        Wv x + bv    (direct)
// grid (NV/64, CRED/64, 3), block 256
// ---------------------------------------------------------------------------
__global__ __launch_bounds__(256) void qkv_kernel(
    const float* __restrict__ x,
    const float* __restrict__ Wq, const float* __restrict__ bq,
    const float* __restrict__ Wk, const float* __restrict__ bk,
    const float* __restrict__ Wv, const float* __restrict__ bv)
{
    __shared__ float Ws[64][65];
    __shared__ float Bs[64][64];

    const float* W; const float* bias;
    if (blockIdx.z == 0)      { W = Wq; bias = bq; }
    else if (blockIdx.z == 1) { W = Wk; bias = bk; }
    else                      { W = Wv; bias = bv; }

    const int n0 = blockIdx.x * 64;
    const int o0 = blockIdx.y * 64;
    const int tid = threadIdx.x;
    const int tx = tid & 15, ty = tid >> 4;

    float acc[4][4] = {};

    for (int k0 = 0; k0 < CIN; k0 += 64) {
        __syncthreads();
        for (int i = tid; i < 64 * 64; i += 256) {
            int r = i >> 6, c = i & 63;
            Ws[r][c] = W[(o0 + r) * CIN + k0 + c];
        }
        for (int i = tid; i < 64 * 16; i += 256) {
            int r = i >> 4, c4 = (i & 15) << 2;
            *(float4*)&Bs[r][c4] = *(const float4*)&x[(k0 + r) * NV + n0 + c4];
        }
        __syncthreads();
        #pragma unroll 16
        for (int kk = 0; kk < 64; kk++) {
            float a0 = Ws[4*ty+0][kk], a1 = Ws[4*ty+1][kk];
            float a2 = Ws[4*ty+2][kk], a3 = Ws[4*ty+3][kk];
            float4 b = *(float4*)&Bs[kk][4*tx];
            acc[0][0]+=a0*b.x; acc[0][1]+=a0*b.y; acc[0][2]+=a0*b.z; acc[0][3]+=a0*b.w;
            acc[1][0]+=a1*b.x; acc[1][1]+=a1*b.y; acc[1][2]+=a1*b.z; acc[1][3]+=a1*b.w;
            acc[2][0]+=a2*b.x; acc[2][1]+=a2*b.y; acc[2][2]+=a2*b.z; acc[2][3]+=a2*b.w;
            acc[3][0]+=a3*b.x; acc[3][1]+=a3*b.y; acc[3][2]+=a3*b.z; acc[3][3]+=a3*b.w;
        }
    }

    if (blockIdx.z == 2) {
        // V: direct bf16 store to [d][N]
        #pragma unroll
        for (int i = 0; i < 4; i++) {
            int o = o0 + 4*ty + i;
            float bb = bias[o];
            uint2 pk;
            pk.x = packbf(acc[i][0] + bb, acc[i][1] + bb);
            pk.y = packbf(acc[i][2] + bb, acc[i][3] + bb);
            *(uint2*)&g_Vh[o * NV + n0 + 4*tx] = pk;
        }
    } else {
        const float scale = (blockIdx.z == 0) ? ATTN_SCALE : 1.0f;
        __nv_bfloat16* dst = (blockIdx.z == 0) ? g_Qh : g_Kh;
        __syncthreads();
        #pragma unroll
        for (int i = 0; i < 4; i++) {
            int o = 4*ty + i;
            float bb = bias[o0 + o];
            Ws[o][4*tx+0] = (acc[i][0] + bb) * scale;
            Ws[o][4*tx+1] = (acc[i][1] + bb) * scale;
            Ws[o][4*tx+2] = (acc[i][2] + bb) * scale;
            Ws[o][4*tx+3] = (acc[i][3] + bb) * scale;
        }
        __syncthreads();
        for (int i = tid; i < 2048; i += 256) {
            int n = i >> 5, w = i & 31;
            uint32_t v = packbf(Ws[2*w][n], Ws[2*w+1][n]);
            *(uint32_t*)&dst[(n0 + n) * CRED + o0 + 2*w] = v;
        }
    }
}

// ---------------------------------------------------------------------------
// Kernel 2: bf16 flash attention, mma.sync.m16n8k16.
// CTA: 64 Q rows, 4 warps (16 rows each), 128 threads. grid = NV/64 = 256.
// KV tile 64, double-buffered. SMEM 80KB -> 2 CTAs/SM.
//   Qs [64][256B]  swizzled (chunk c -> c^(row&7))
//   Ks [2][64][256B], Vs [2][128][128B]
// ---------------------------------------------------------------------------
extern __shared__ char sm_attn[];

__global__ __launch_bounds__(128) void attn_kernel()
{
    const uint32_t sbase = smem_u32(sm_attn);
    const uint32_t QS  = sbase;
    const uint32_t KS0 = sbase + 16384, KS1 = sbase + 32768;
    const uint32_t VS0 = sbase + 49152, VS1 = sbase + 65536;

    const int tid = threadIdx.x;
    const int lane = tid & 31, warp = tid >> 5;
    const int n0 = blockIdx.x * 64;
    const int wr = warp * 16;
    const int lr = lane & 7, g = lane >> 3;

    // Stage Q (once): 64 rows x 16 chunks
    for (int i = tid; i < 1024; i += 128) {
        int r = i >> 4, cc = i & 15;
        CP_ASYNC16(QS + r * 256 + ((cc ^ (r & 7)) << 4), &g_Qh[(n0 + r) * CRED + cc * 8]);
    }
    // Stage K/V tile 0
    for (int i = tid; i < 1024; i += 128) {
        int r = i >> 4, cc = i & 15;
        CP_ASYNC16(KS0 + r * 256 + ((cc ^ (r & 7)) << 4), &g_Kh[r * CRED + cc * 8]);
    }
    for (int i = tid; i < 1024; i += 128) {
        int r = i >> 3, cc = i & 7;
        CP_ASYNC16(VS0 + r * 128 + ((cc ^ (r & 7)) << 4), &g_Vh[r * NV + cc * 8]);
    }
    CP_COMMIT();

    float oAcc[16][4];
    #pragma unroll
    for (int i = 0; i < 16; i++) { oAcc[i][0]=0; oAcc[i][1]=0; oAcc[i][2]=0; oAcc[i][3]=0; }
    float m0 = -1e30f, m1 = -1e30f, l0 = 0.0f, l1 = 0.0f;

    const int T = NV / 64;   // 256 kv tiles
    for (int t = 0; t < T; t++) {
        CP_WAIT0();
        __syncthreads();
        const uint32_t KS = (t & 1) ? KS1 : KS0;
        const uint32_t VS = (t & 1) ? VS1 : VS0;
        if (t + 1 < T) {
            const int kt = (t + 1) * 64;
            const uint32_t KSn = (t & 1) ? KS0 : KS1;
            const uint32_t VSn = (t & 1) ? VS0 : VS1;
            for (int i = tid; i < 1024; i += 128) {
                int r = i >> 4, cc = i & 15;
                CP_ASYNC16(KSn + r * 256 + ((cc ^ (r & 7)) << 4),
                           &g_Kh[(kt + r) * CRED + cc * 8]);
            }
            for (int i = tid; i < 1024; i += 128) {
                int r = i >> 3, cc = i & 7;
                CP_ASYNC16(VSn + r * 128 + ((cc ^ (r & 7)) << 4),
                           &g_Vh[r * NV + kt + cc * 8]);
            }
            CP_COMMIT();
        }

        // ---- S = Q @ K^T (16 rows x 64 cols per warp) ----
        float sAcc[8][4];
        #pragma unroll
        for (int i = 0; i < 8; i++) { sAcc[i][0]=0; sAcc[i][1]=0; sAcc[i][2]=0; sAcc[i][3]=0; }

        #pragma unroll
        for (int kk = 0; kk < 8; kk++) {
            int arow = wr + lr + ((g & 1) << 3);
            int akc = (kk << 1) + (g >> 1);
            uint32_t a0, a1, a2, a3;
            LDSM4(a0, a1, a2, a3, QS + arow * 256 + ((akc ^ (arow & 7)) << 4));
            #pragma unroll
            for (int np = 0; np < 4; np++) {
                int brow = (np << 4) + lr + ((g >> 1) << 3);
                int bkc = (kk << 1) + (g & 1);
                uint32_t b0, b1, b2, b3;
                LDSM4(b0, b1, b2, b3, KS + brow * 256 + ((bkc ^ (brow & 7)) << 4));
                MMA16816(sAcc[2*np],   a0, a1, a2, a3, b0, b1);
                MMA16816(sAcc[2*np+1], a0, a1, a2, a3, b2, b3);
            }
        }

        // ---- online softmax ----
        float mx0 = -1e30f, mx1 = -1e30f;
        #pragma unroll
        for (int nt = 0; nt < 8; nt++) {
            mx0 = fmaxf(mx0, fmaxf(sAcc[nt][0], sAcc[nt][1]));
            mx1 = fmaxf(mx1, fmaxf(sAcc[nt][2], sAcc[nt][3]));
        }
        mx0 = fmaxf(mx0, __shfl_xor_sync(0xffffffffu, mx0, 1));
        mx0 = fmaxf(mx0, __shfl_xor_sync(0xffffffffu, mx0, 2));
        mx1 = fmaxf(mx1, __shfl_xor_sync(0xffffffffu, mx1, 1));
        mx1 = fmaxf(mx1, __shfl_xor_sync(0xffffffffu, mx1, 2));
        float mn0 = fmaxf(m0, mx0), mn1 = fmaxf(m1, mx1);
        float f0 = __expf(m0 - mn0), f1 = __expf(m1 - mn1);
        m0 = mn0; m1 = mn1;
        l0 *= f0; l1 *= f1;
        float s0 = 0.0f, s1 = 0.0f;
        #pragma unroll
        for (int nt = 0; nt < 8; nt++) {
            float p;
            p = __expf(sAcc[nt][0] - m0); sAcc[nt][0] = p; s0 += p;
            p = __expf(sAcc[nt][1] - m0); sAcc[nt][1] = p; s0 += p;
            p = __expf(sAcc[nt][2] - m1); sAcc[nt][2] = p; s1 += p;
            p = __expf(sAcc[nt][3] - m1); sAcc[nt][3] = p; s1 += p;
        }
        l0 += s0; l1 += s1;
        #pragma unroll
        for (int dt = 0; dt < 16; dt++) {
            oAcc[dt][0] *= f0; oAcc[dt][1] *= f0;
            oAcc[dt][2] *= f1; oAcc[dt][3] *= f1;
        }

        // ---- O += P @ V ----
        #pragma unroll
        for (int kk = 0; kk < 4; kk++) {
            uint32_t a0 = packbf(sAcc[2*kk][0],   sAcc[2*kk][1]);
            uint32_t a1 = packbf(sAcc[2*kk][2],   sAcc[2*kk][3]);
            uint32_t a2 = packbf(sAcc[2*kk+1][0], sAcc[2*kk+1][1]);
            uint32_t a3 = packbf(sAcc[2*kk+1][2], sAcc[2*kk+1][3]);
            #pragma unroll
            for (int dp = 0; dp < 8; dp++) {
                int vrow = (dp << 4) + lr + ((g >> 1) << 3);
                int vkc = (kk << 1) + (g & 1);
                uint32_t b0, b1, b2, b3;
                LDSM4(b0, b1, b2, b3, VS + vrow * 128 + ((vkc ^ (vrow & 7)) << 4));
                MMA16816(oAcc[2*dp],   a0, a1, a2, a3, b0, b1);
                MMA16816(oAcc[2*dp+1], a0, a1, a2, a3, b2, b3);
            }
        }
        __syncthreads();
    }

    // epilogue
    l0 += __shfl_xor_sync(0xffffffffu, l0, 1);
    l0 += __shfl_xor_sync(0xffffffffu, l0, 2);
    l1 += __shfl_xor_sync(0xffffffffu, l1, 1);
    l1 += __shfl_xor_sync(0xffffffffu, l1, 2);
    const float inv0 = 1.0f / l0, inv1 = 1.0f / l1;
    const int row_lo = n0 + wr + (lane >> 2);
    const int row_hi = row_lo + 8;
    #pragma unroll
    for (int dt = 0; dt < 16; dt++) {
        int d = dt * 8 + 2 * (lane & 3);
        float2 vlo = make_float2(oAcc[dt][0] * inv0, oAcc[dt][1] * inv0);
        float2 vhi = make_float2(oAcc[dt][2] * inv1, oAcc[dt][3] * inv1);
        *(float2*)&g_Oa[row_lo * CRED + d] = vlo;
        *(float2*)&g_Oa[row_hi * CRED + d] = vhi;
    }
}

// ---------------------------------------------------------------------------
// Kernel 3: output projection + residual (fp32)
// ---------------------------------------------------------------------------
__global__ __launch_bounds__(256) void proj_kernel(
    const float* __restrict__ x, const float* __restrict__ Wo,
    const float* __restrict__ bo, float* __restrict__ out)
{
    __shared__ float Ws[64][65];
    __shared__ float Bs[64][65];

    const int n0 = blockIdx.x * 64;
    const int o0 = blockIdx.y * 64;
    const int tid = threadIdx.x;
    const int tx = tid & 15, ty = tid >> 4;

    float acc[4][4] = {};

    for (int k0 = 0; k0 < CRED; k0 += 64) {
        __syncthreads();
        for (int i = tid; i < 4096; i += 256) {
            int r = i >> 6, c = i & 63;
            Ws[r][c] = Wo[(o0 + r) * CRED + k0 + c];
        }
        for (int i = tid; i < 4096; i += 256) {
            int n = i >> 6, k = i & 63;
            Bs[k][n] = g_Oa[(n0 + n) * CRED + k0 + k];
        }
        __syncthreads();
        #pragma unroll 16
        for (int kk = 0; kk < 64; kk++) {
            float a0 = Ws[4*ty+0][kk], a1 = Ws[4*ty+1][kk];
            float a2 = Ws[4*ty+2][kk], a3 = Ws[4*ty+3][kk];
            float b0 = Bs[kk][4*tx+0], b1 = Bs[kk][4*tx+1];
            float b2 = Bs[kk][4*tx+2], b3 = Bs[kk][4*tx+3];
            acc[0][0]+=a0*b0; acc[0][1]+=a0*b1; acc[0][2]+=a0*b2; acc[0][3]+=a0*b3;
            acc[1][0]+=a1*b0; acc[1][1]+=a1*b1; acc[1][2]+=a1*b2; acc[1][3]+=a1*b3;
            acc[2][0]+=a2*b0; acc[2][1]+=a2*b1; acc[2][2]+=a2*b2; acc[2][3]+=a2*b3;
            acc[3][0]+=a3*b0; acc[3][1]+=a3*b1; acc[3][2]+=a3*b2; acc[3][3]+=a3*b3;
        }
    }
    #pragma unroll
    for (int i = 0; i < 4; i++) {
        int o = o0 + 4*ty + i;
        float bb = bo[o];
        const float4 xi = *(const float4*)&x[o * NV + n0 + 4*tx];
        float4 r;
        r.x = xi.x + acc[i][0] + bb;
        r.y = xi.y + acc[i][1] + bb;
        r.z = xi.z + acc[i][2] + bb;
        r.w = xi.w + acc[i][3] + bb;
        *(float4*)&out[o * NV + n0 + 4*tx] = r;
    }
}

// ---------------------------------------------------------------------------
extern "C" void kernel_launch(void* const* d_in, const int* in_sizes, int n_in,
                              void* d_out, int out_size)
{
    const float* x  = (const float*)d_in[0];
    const float* Wq = (const float*)d_in[1];
    const float* bq = (const float*)d_in[2];
    const float* Wk = (const float*)d_in[3];
    const float* bk = (const float*)d_in[4];
    const float* Wv = (const float*)d_in[5];
    const float* bv = (const float*)d_in[6];
    const float* Wo = (const float*)d_in[7];
    const float* bo = (const float*)d_in[8];
    float* out = (float*)d_out;

    qkv_kernel<<<dim3(NV/64, CRED/64, 3), 256>>>(x, Wq, bq, Wk, bk, Wv, bv);

    const int attn_smem = 81920;   // Q 16K + K 2x16K + V 2x16K
    cudaFuncSetAttribute(attn_kernel, cudaFuncAttributeMaxDynamicSharedMemorySize, attn_smem);
    attn_kernel<<<NV/64, 128, attn_smem>>>();

    proj_kernel<<<dim3(NV/64, CIN/64), 256>>>(x, Wo, bo, out);
}

// round 6
// speedup vs baseline: 9.0114x; 1.1915x over previous
#include <cuda_runtime.h>
#include <cuda_bf16.h>
#include <cstdint>
#include <math.h>

#define NV   16384   // D*H*W
#define CIN  256
#define CRED 128
#define ATTN_SCALE 0.0625f   // 1/sqrt(CIN)

// Scratch (device globals, allocation-free)
__device__ __align__(16) __nv_bfloat16 g_Oa[NV * CRED];  // [n][d] attention out bf16
__device__ __align__(16) __nv_bfloat16 g_Qh[NV * CRED];  // [n][d], pre-scaled
__device__ __align__(16) __nv_bfloat16 g_Kh[NV * CRED];  // [n][d]
__device__ __align__(16) __nv_bfloat16 g_Vh[CRED * NV];  // [d][n]

// ---------------------------------------------------------------------------
// PTX helpers
// ---------------------------------------------------------------------------
__device__ __forceinline__ uint32_t smem_u32(const void* p) {
    return (uint32_t)__cvta_generic_to_shared(p);
}
#define CP_ASYNC16(dst, src) \
    asm volatile("cp.async.cg.shared.global [%0], [%1], 16;\n" :: "r"(dst), "l"(src))
#define CP_COMMIT() asm volatile("cp.async.commit_group;\n" ::: "memory")
#define CP_WAIT0()  asm volatile("cp.async.wait_group 0;\n" ::: "memory")

#define LDSM4(r0, r1, r2, r3, addr) \
    asm volatile("ldmatrix.sync.aligned.m8n8.x4.shared.b16 {%0,%1,%2,%3}, [%4];" \
                 : "=r"(r0), "=r"(r1), "=r"(r2), "=r"(r3) : "r"(addr))

#define MMA16816(c, a0, a1, a2, a3, b0, b1) \
    asm volatile("mma.sync.aligned.m16n8k16.row.col.f32.bf16.bf16.f32 " \
                 "{%0,%1,%2,%3}, {%4,%5,%6,%7}, {%8,%9}, {%0,%1,%2,%3};" \
                 : "+f"(c[0]), "+f"(c[1]), "+f"(c[2]), "+f"(c[3]) \
                 : "r"(a0), "r"(a1), "r"(a2), "r"(a3), "r"(b0), "r"(b1))

__device__ __forceinline__ uint32_t packbf(float lo, float hi) {
    uint32_t d;
    asm("cvt.rn.bf16x2.f32 %0, %1, %2;" : "=r"(d) : "f"(hi), "f"(lo));
    return d;
}

// ---------------------------------------------------------------------------
// Kernel 1: QKV projection via bf16 mma.sync.
// z=0: Qh[n][d] = scale*(Wq x + bq);  z=1: Kh[n][d];  z=2: Vh[d][n].
// CTA: 128 n x 128 d, K=256 in 4 chunks of 64. block 256 (8 warps).
// smem: XT[128n][64c] bf16 (x transposed+converted), WT[128d][64c] bf16.
// Rows are 128B (8 chunks of 16B), swizzle chunk c -> c^(row&7).
// For z<2: A=XT (rows n), B=WT (rows d). For z=2: swap roles.
// ---------------------------------------------------------------------------
__global__ __launch_bounds__(256) void qkv_mma(
    const float* __restrict__ x,
    const float* __restrict__ Wq, const float* __restrict__ bq,
    const float* __restrict__ Wk, const float* __restrict__ bk,
    const float* __restrict__ Wv, const float* __restrict__ bv)
{
    __shared__ __align__(16) char smc[32768];   // XT 16KB + WT 16KB
    const uint32_t XTu = smem_u32(smc);
    const uint32_t WTu = XTu + 16384;

    const int z = blockIdx.y;
    const float* W; const float* bias;
    if (z == 0)      { W = Wq; bias = bq; }
    else if (z == 1) { W = Wk; bias = bk; }
    else             { W = Wv; bias = bv; }

    const int n0 = blockIdx.x * 128;
    const int tid = threadIdx.x;
    const int lane = tid & 31, warp = tid >> 5;
    const int wr = warp * 16;
    const int lr = lane & 7, g = lane >> 3;

    float acc[16][4];
    #pragma unroll
    for (int i = 0; i < 16; i++) { acc[i][0]=0; acc[i][1]=0; acc[i][2]=0; acc[i][3]=0; }

    for (int k0 = 0; k0 < CIN; k0 += 64) {
        __syncthreads();
        // Stage XT: transpose x[64c][128n] fp32 -> XT[n][c] bf16 (2 c per thread)
        for (int i = tid; i < 4096; i += 256) {
            int c2 = i >> 7, n = i & 127;
            float v0 = x[(k0 + 2*c2)     * NV + n0 + n];
            float v1 = x[(k0 + 2*c2 + 1) * NV + n0 + n];
            uint32_t off = n * 128 + ((((c2 >> 2) ^ (n & 7))) << 4) + ((4*c2) & 12);
            *(uint32_t*)&smc[off] = packbf(v0, v1);
        }
        // Stage WT: W[128d][64c] fp32 -> bf16
        for (int i = tid; i < 4096; i += 256) {
            int d = i >> 5, c2 = i & 31;
            float2 wv = *(const float2*)&W[d * CIN + k0 + 2*c2];
            uint32_t off = d * 128 + ((((c2 >> 2) ^ (d & 7))) << 4) + ((4*c2) & 12);
            *(uint32_t*)&smc[16384 + off] = packbf(wv.x, wv.y);
        }
        __syncthreads();

        const uint32_t Ab = (z == 2) ? WTu : XTu;
        const uint32_t Bb = (z == 2) ? XTu : WTu;
        #pragma unroll
        for (int kk = 0; kk < 4; kk++) {
            int arow = wr + lr + ((g & 1) << 3);
            int akc = (kk << 1) + (g >> 1);
            uint32_t a0, a1, a2, a3;
            LDSM4(a0, a1, a2, a3, Ab + arow * 128 + ((akc ^ (arow & 7)) << 4));
            #pragma unroll
            for (int np = 0; np < 8; np++) {
                int brow = (np << 4) + lr + ((g >> 1) << 3);
                int bkc = (kk << 1) + (g & 1);
                uint32_t b0, b1, b2, b3;
                LDSM4(b0, b1, b2, b3, Bb + brow * 128 + ((bkc ^ (brow & 7)) << 4));
                MMA16816(acc[2*np],   a0, a1, a2, a3, b0, b1);
                MMA16816(acc[2*np+1], a0, a1, a2, a3, b2, b3);
            }
        }
    }

    const int r_lo = wr + (lane >> 2), r_hi = r_lo + 8;
    if (z < 2) {
        // rows = n, cols = d
        __nv_bfloat16* dst = (z == 0) ? g_Qh : g_Kh;
        const float scale = (z == 0) ? ATTN_SCALE : 1.0f;
        #pragma unroll
        for (int f = 0; f < 16; f++) {
            int d = ((f >> 1) << 4) + ((f & 1) << 3) + ((lane & 3) << 1);
            float b0 = bias[d], b1 = bias[d + 1];
            *(uint32_t*)&dst[(n0 + r_lo) * CRED + d] =
                packbf((acc[f][0] + b0) * scale, (acc[f][1] + b1) * scale);
            *(uint32_t*)&dst[(n0 + r_hi) * CRED + d] =
                packbf((acc[f][2] + b0) * scale, (acc[f][3] + b1) * scale);
        }
    } else {
        // rows = d, cols = n
        const float blo = bias[r_lo], bhi = bias[r_hi];
        #pragma unroll
        for (int f = 0; f < 16; f++) {
            int n = ((f >> 1) << 4) + ((f & 1) << 3) + ((lane & 3) << 1);
            *(uint32_t*)&g_Vh[r_lo * NV + n0 + n] = packbf(acc[f][0] + blo, acc[f][1] + blo);
            *(uint32_t*)&g_Vh[r_hi * NV + n0 + n] = packbf(acc[f][2] + bhi, acc[f][3] + bhi);
        }
    }
}

// ---------------------------------------------------------------------------
// Kernel 2: bf16 flash attention, mma.sync.m16n8k16 (unchanged core).
// CTA: 64 Q rows, 4 warps, 128 threads. grid 256. KV tile 64, double-buffered.
// SMEM 80KB -> 2 CTAs/SM. Epilogue now writes bf16 g_Oa.
// ---------------------------------------------------------------------------
extern __shared__ char sm_attn[];

__global__ __launch_bounds__(128) void attn_kernel()
{
    const uint32_t sbase = smem_u32(sm_attn);
    const uint32_t QS  = sbase;
    const uint32_t KS0 = sbase + 16384, KS1 = sbase + 32768;
    const uint32_t VS0 = sbase + 49152, VS1 = sbase + 65536;

    const int tid = threadIdx.x;
    const int lane = tid & 31, warp = tid >> 5;
    const int n0 = blockIdx.x * 64;
    const int wr = warp * 16;
    const int lr = lane & 7, g = lane >> 3;

    for (int i = tid; i < 1024; i += 128) {
        int r = i >> 4, cc = i & 15;
        CP_ASYNC16(QS + r * 256 + ((cc ^ (r & 7)) << 4), &g_Qh[(n0 + r) * CRED + cc * 8]);
    }
    for (int i = tid; i < 1024; i += 128) {
        int r = i >> 4, cc = i & 15;
        CP_ASYNC16(KS0 + r * 256 + ((cc ^ (r & 7)) << 4), &g_Kh[r * CRED + cc * 8]);
    }
    for (int i = tid; i < 1024; i += 128) {
        int r = i >> 3, cc = i & 7;
        CP_ASYNC16(VS0 + r * 128 + ((cc ^ (r & 7)) << 4), &g_Vh[r * NV + cc * 8]);
    }
    CP_COMMIT();

    float oAcc[16][4];
    #pragma unroll
    for (int i = 0; i < 16; i++) { oAcc[i][0]=0; oAcc[i][1]=0; oAcc[i][2]=0; oAcc[i][3]=0; }
    float m0 = -1e30f, m1 = -1e30f, l0 = 0.0f, l1 = 0.0f;

    const int T = NV / 64;
    for (int t = 0; t < T; t++) {
        CP_WAIT0();
        __syncthreads();
        const uint32_t KS = (t & 1) ? KS1 : KS0;
        const uint32_t VS = (t & 1) ? VS1 : VS0;
        if (t + 1 < T) {
            const int kt = (t + 1) * 64;
            const uint32_t KSn = (t & 1) ? KS0 : KS1;
            const uint32_t VSn = (t & 1) ? VS0 : VS1;
            for (int i = tid; i < 1024; i += 128) {
                int r = i >> 4, cc = i & 15;
                CP_ASYNC16(KSn + r * 256 + ((cc ^ (r & 7)) << 4),
                           &g_Kh[(kt + r) * CRED + cc * 8]);
            }
            for (int i = tid; i < 1024; i += 128) {
                int r = i >> 3, cc = i & 7;
                CP_ASYNC16(VSn + r * 128 + ((cc ^ (r & 7)) << 4),
                           &g_Vh[r * NV + kt + cc * 8]);
            }
            CP_COMMIT();
        }

        float sAcc[8][4];
        #pragma unroll
        for (int i = 0; i < 8; i++) { sAcc[i][0]=0; sAcc[i][1]=0; sAcc[i][2]=0; sAcc[i][3]=0; }

        #pragma unroll
        for (int kk = 0; kk < 8; kk++) {
            int arow = wr + lr + ((g & 1) << 3);
            int akc = (kk << 1) + (g >> 1);
            uint32_t a0, a1, a2, a3;
            LDSM4(a0, a1, a2, a3, QS + arow * 256 + ((akc ^ (arow & 7)) << 4));
            #pragma unroll
            for (int np = 0; np < 4; np++) {
                int brow = (np << 4) + lr + ((g >> 1) << 3);
                int bkc = (kk << 1) + (g & 1);
                uint32_t b0, b1, b2, b3;
                LDSM4(b0, b1, b2, b3, KS + brow * 256 + ((bkc ^ (brow & 7)) << 4));
                MMA16816(sAcc[2*np],   a0, a1, a2, a3, b0, b1);
                MMA16816(sAcc[2*np+1], a0, a1, a2, a3, b2, b3);
            }
        }

        float mx0 = -1e30f, mx1 = -1e30f;
        #pragma unroll
        for (int nt = 0; nt < 8; nt++) {
            mx0 = fmaxf(mx0, fmaxf(sAcc[nt][0], sAcc[nt][1]));
            mx1 = fmaxf(mx1, fmaxf(sAcc[nt][2], sAcc[nt][3]));
        }
        mx0 = fmaxf(mx0, __shfl_xor_sync(0xffffffffu, mx0, 1));
        mx0 = fmaxf(mx0, __shfl_xor_sync(0xffffffffu, mx0, 2));
        mx1 = fmaxf(mx1, __shfl_xor_sync(0xffffffffu, mx1, 1));
        mx1 = fmaxf(mx1, __shfl_xor_sync(0xffffffffu, mx1, 2));
        float mn0 = fmaxf(m0, mx0), mn1 = fmaxf(m1, mx1);
        float f0 = __expf(m0 - mn0), f1 = __expf(m1 - mn1);
        m0 = mn0; m1 = mn1;
        l0 *= f0; l1 *= f1;
        float s0 = 0.0f, s1 = 0.0f;
        #pragma unroll
        for (int nt = 0; nt < 8; nt++) {
            float p;
            p = __expf(sAcc[nt][0] - m0); sAcc[nt][0] = p; s0 += p;
            p = __expf(sAcc[nt][1] - m0); sAcc[nt][1] = p; s0 += p;
            p = __expf(sAcc[nt][2] - m1); sAcc[nt][2] = p; s1 += p;
            p = __expf(sAcc[nt][3] - m1); sAcc[nt][3] = p; s1 += p;
        }
        l0 += s0; l1 += s1;
        #pragma unroll
        for (int dt = 0; dt < 16; dt++) {
            oAcc[dt][0] *= f0; oAcc[dt][1] *= f0;
            oAcc[dt][2] *= f1; oAcc[dt][3] *= f1;
        }

        #pragma unroll
        for (int kk = 0; kk < 4; kk++) {
            uint32_t a0 = packbf(sAcc[2*kk][0],   sAcc[2*kk][1]);
            uint32_t a1 = packbf(sAcc[2*kk][2],   sAcc[2*kk][3]);
            uint32_t a2 = packbf(sAcc[2*kk+1][0], sAcc[2*kk+1][1]);
            uint32_t a3 = packbf(sAcc[2*kk+1][2], sAcc[2*kk+1][3]);
            #pragma unroll
            for (int dp = 0; dp < 8; dp++) {
                int vrow = (dp << 4) + lr + ((g >> 1) << 3);
                int vkc = (kk << 1) + (g & 1);
                uint32_t b0, b1, b2, b3;
                LDSM4(b0, b1, b2, b3, VS + vrow * 128 + ((vkc ^ (vrow & 7)) << 4));
                MMA16816(oAcc[2*dp],   a0, a1, a2, a3, b0, b1);
                MMA16816(oAcc[2*dp+1], a0, a1, a2, a3, b2, b3);
            }
        }
        __syncthreads();
    }

    l0 += __shfl_xor_sync(0xffffffffu, l0, 1);
    l0 += __shfl_xor_sync(0xffffffffu, l0, 2);
    l1 += __shfl_xor_sync(0xffffffffu, l1, 1);
    l1 += __shfl_xor_sync(0xffffffffu, l1, 2);
    const float inv0 = 1.0f / l0, inv1 = 1.0f / l1;
    const int row_lo = n0 + wr + (lane >> 2);
    const int row_hi = row_lo + 8;
    #pragma unroll
    for (int dt = 0; dt < 16; dt++) {
        int d = dt * 8 + 2 * (lane & 3);
        *(uint32_t*)&g_Oa[row_lo * CRED + d] = packbf(oAcc[dt][0] * inv0, oAcc[dt][1] * inv0);
        *(uint32_t*)&g_Oa[row_hi * CRED + d] = packbf(oAcc[dt][2] * inv1, oAcc[dt][3] * inv1);
    }
}

// ---------------------------------------------------------------------------
// Kernel 3: output projection + residual via bf16 mma.sync.
// out[o][n] = x[o][n] + sum_k Wo[o][k]*Oa[n][k] + bo[o]
// CTA: 128 o x 128 n, K=128 single shot. block 256 (8 warps).
// smem (dynamic 64KB): WoT[128o][128k] bf16 swizzled, OaT[128n][128k] bf16.
// ---------------------------------------------------------------------------
extern __shared__ char sm_proj[];

__global__ __launch_bounds__(256) void proj_mma(
    const float* __restrict__ x, const float* __restrict__ Wo,
    const float* __restrict__ bo, float* __restrict__ out)
{
    const uint32_t WTu = smem_u32(sm_proj);
    const uint32_t OTu = WTu + 32768;

    const int n0 = blockIdx.x * 128;
    const int o0 = blockIdx.y * 128;
    const int tid = threadIdx.x;
    const int lane = tid & 31, warp = tid >> 5;
    const int wr = warp * 16;
    const int lr = lane & 7, g = lane >> 3;

    // Stage Oa via cp.async (already bf16, row = 256B, 16 chunks)
    for (int i = tid; i < 2048; i += 256) {
        int r = i >> 4, cc = i & 15;
        CP_ASYNC16(OTu + r * 256 + ((cc ^ (r & 7)) << 4), &g_Oa[(n0 + r) * CRED + cc * 8]);
    }
    CP_COMMIT();
    // Stage Wo fp32 -> bf16 (rows o, 16 chunks)
    for (int i = tid; i < 8192; i += 256) {
        int o = i >> 6, c2 = i & 63;
        float2 wv = *(const float2*)&Wo[(o0 + o) * CRED + 2*c2];
        uint32_t off = o * 256 + ((((c2 >> 2) ^ (o & 7))) << 4) + ((4*c2) & 12);
        *(uint32_t*)&sm_proj[off] = packbf(wv.x, wv.y);
    }
    CP_WAIT0();
    __syncthreads();

    float acc[16][4];
    #pragma unroll
    for (int i = 0; i < 16; i++) { acc[i][0]=0; acc[i][1]=0; acc[i][2]=0; acc[i][3]=0; }

    #pragma unroll
    for (int kk = 0; kk < 8; kk++) {
        int arow = wr + lr + ((g & 1) << 3);
        int akc = (kk << 1) + (g >> 1);
        uint32_t a0, a1, a2, a3;
        LDSM4(a0, a1, a2, a3, WTu + arow * 256 + ((akc ^ (arow & 7)) << 4));
        #pragma unroll
        for (int np = 0; np < 8; np++) {
            int brow = (np << 4) + lr + ((g >> 1) << 3);
            int bkc = (kk << 1) + (g & 1);
            uint32_t b0, b1, b2, b3;
            LDSM4(b0, b1, b2, b3, OTu + brow * 256 + ((bkc ^ (brow & 7)) << 4));
            MMA16816(acc[2*np],   a0, a1, a2, a3, b0, b1);
            MMA16816(acc[2*np+1], a0, a1, a2, a3, b2, b3);
        }
    }

    const int o_lo = o0 + wr + (lane >> 2), o_hi = o_lo + 8;
    const float blo = bo[o_lo], bhi = bo[o_hi];
    #pragma unroll
    for (int f = 0; f < 16; f++) {
        int n = n0 + ((f >> 1) << 4) + ((f & 1) << 3) + ((lane & 3) << 1);
        const float2 xlo = *(const float2*)&x[o_lo * NV + n];
        const float2 xhi = *(const float2*)&x[o_hi * NV + n];
        float2 rlo = make_float2(xlo.x + acc[f][0] + blo, xlo.y + acc[f][1] + blo);
        float2 rhi = make_float2(xhi.x + acc[f][2] + bhi, xhi.y + acc[f][3] + bhi);
        *(float2*)&out[o_lo * NV + n] = rlo;
        *(float2*)&out[o_hi * NV + n] = rhi;
    }
}

// ---------------------------------------------------------------------------
extern "C" void kernel_launch(void* const* d_in, const int* in_sizes, int n_in,
                              void* d_out, int out_size)
{
    const float* x  = (const float*)d_in[0];
    const float* Wq = (const float*)d_in[1];
    const float* bq = (const float*)d_in[2];
    const float* Wk = (const float*)d_in[3];
    const float* bk = (const float*)d_in[4];
    const float* Wv = (const float*)d_in[5];
    const float* bv = (const float*)d_in[6];
    const float* Wo = (const float*)d_in[7];
    const float* bo = (const float*)d_in[8];
    float* out = (float*)d_out;

    qkv_mma<<<dim3(NV/128, 3), 256>>>(x, Wq, bq, Wk, bk, Wv, bv);

    const int attn_smem = 81920;
    cudaFuncSetAttribute(attn_kernel, cudaFuncAttributeMaxDynamicSharedMemorySize, attn_smem);
    attn_kernel<<<NV/64, 128, attn_smem>>>();

    const int proj_smem = 65536;
    cudaFuncSetAttribute(proj_mma, cudaFuncAttributeMaxDynamicSharedMemorySize, proj_smem);
    proj_mma<<<dim3(NV/128, CIN/128), 256, proj_smem>>>(x, Wo, bo, out);
}